// round 1
// baseline (speedup 1.0000x reference)
#include <cuda_runtime.h>
#include <math.h>

// ---------------- problem constants ----------------
#define LSEQ 2048
#define DMODEL 1024
#define NHEAD 16
#define HDIM 64
#define NLYR 4
#define WIN 256
#define IDIM 3280
#define VDIM 32000
#define EPSV 1e-5f

// ---------------- scratch (static device globals; no runtime alloc) ----------------
__device__ float g_x[LSEQ * DMODEL];     // residual stream
__device__ float g_xn[LSEQ * DMODEL];    // normed activations
__device__ float g_q[LSEQ * DMODEL];
__device__ float g_k[LSEQ * DMODEL];
__device__ float g_v[LSEQ * DMODEL];
__device__ float g_attn[LSEQ * DMODEL];
__device__ float g_z1[LSEQ * IDIM];      // z1, then silu(z1)*z3 in-place
__device__ float g_z3[LSEQ * IDIM];

// ---------------- embedding gather ----------------
__global__ void embed_kernel(const int* __restrict__ tokens,
                             const float* __restrict__ ew,
                             float* __restrict__ x) {
    int i = blockIdx.x;
    int tok = tokens[i];
    const float4* src = (const float4*)(ew + (size_t)tok * DMODEL);
    float4* dst = (float4*)(x + (size_t)i * DMODEL);
    dst[threadIdx.x] = src[threadIdx.x];   // 256 threads * 4 floats = 1024
}

// ---------------- row RMSNorm (D=1024), replicates guards ----------------
__global__ void rmsnorm_kernel(const float* __restrict__ x,
                               const float* __restrict__ w,
                               float* __restrict__ y) {
    const int row = blockIdx.x;
    const int t = threadIdx.x;
    const float* xr = x + (size_t)row * DMODEL;
    float v[4];
    float ss = 0.f;
#pragma unroll
    for (int j = 0; j < 4; j++) {
        float a = xr[t + j * 256];
        a = fminf(fmaxf(a, -10000.f), 10000.f);
        v[j] = a;
        ss = fmaf(a, a, ss);
    }
#pragma unroll
    for (int off = 16; off; off >>= 1) ss += __shfl_xor_sync(0xffffffffu, ss, off);
    __shared__ float red[8];
    if ((t & 31) == 0) red[t >> 5] = ss;
    __syncthreads();
    if (t < 32) {
        float s2 = (t < 8) ? red[t] : 0.f;
#pragma unroll
        for (int off = 4; off; off >>= 1) s2 += __shfl_xor_sync(0xffffffffu, s2, off);
        if (t == 0) red[0] = s2;
    }
    __syncthreads();
    float mean = red[0] * (1.f / DMODEL);
    float inv = 1.f / sqrtf(fmaxf(mean, EPSV) + EPSV);
#pragma unroll
    for (int j = 0; j < 4; j++) {
        int c = t + j * 256;
        float r = v[j] * inv * w[c];
        if (!isfinite(r)) r = 0.f;
        y[(size_t)row * DMODEL + c] = r;
    }
}

// ---------------- per-head RMSNorm over 64 dims, in place (one warp per head-row) ----------------
__global__ void rmsnorm_head_kernel(float* __restrict__ q, const float* __restrict__ w) {
    int r = blockIdx.x * (blockDim.x >> 5) + (threadIdx.x >> 5);  // row in [0, L*H)
    int lane = threadIdx.x & 31;
    float* p = q + (size_t)r * HDIM;
    float a0 = p[lane], a1 = p[lane + 32];
    a0 = fminf(fmaxf(a0, -10000.f), 10000.f);
    a1 = fminf(fmaxf(a1, -10000.f), 10000.f);
    float ss = a0 * a0 + a1 * a1;
#pragma unroll
    for (int off = 16; off; off >>= 1) ss += __shfl_xor_sync(0xffffffffu, ss, off);
    float mean = ss * (1.f / HDIM);
    float inv = 1.f / sqrtf(fmaxf(mean, EPSV) + EPSV);
    float r0 = a0 * inv * w[lane];
    float r1 = a1 * inv * w[lane + 32];
    if (!isfinite(r0)) r0 = 0.f;
    if (!isfinite(r1)) r1 = 0.f;
    p[lane] = r0;
    p[lane + 32] = r1;
}

// ---------------- sliding-window causal attention: one block per (query i, head h) ----------------
__global__ void attn_kernel(const float* __restrict__ q, const float* __restrict__ k,
                            const float* __restrict__ v, float* __restrict__ o) {
    const int i = blockIdx.x;
    const int h = blockIdx.y;
    const int t = threadIdx.x;  // 256 threads

    __shared__ float qs[HDIM];
    __shared__ float sc[WIN];
    __shared__ float red[8];
    __shared__ float osum[4][HDIM];

    const int j0 = max(0, i - WIN + 1);
    const int cnt = i - j0 + 1;   // 1..256

    if (t < HDIM) qs[t] = q[(size_t)i * DMODEL + h * HDIM + t];
    __syncthreads();

    float s = -INFINITY;
    if (t < cnt) {
        const float* kr = k + (size_t)(j0 + t) * DMODEL + h * HDIM;
        float a = 0.f;
#pragma unroll
        for (int d = 0; d < HDIM; d++) a = fmaf(qs[d], kr[d], a);
        s = a * 0.125f;  // HD^-0.5
    }
    // block max
    float m = s;
#pragma unroll
    for (int off = 16; off; off >>= 1) m = fmaxf(m, __shfl_xor_sync(0xffffffffu, m, off));
    if ((t & 31) == 0) red[t >> 5] = m;
    __syncthreads();
    if (t < 32) {
        float mm = (t < 8) ? red[t] : -INFINITY;
#pragma unroll
        for (int off = 4; off; off >>= 1) mm = fmaxf(mm, __shfl_xor_sync(0xffffffffu, mm, off));
        if (t == 0) red[0] = mm;
    }
    __syncthreads();
    const float mx = red[0];

    float p = (t < cnt) ? expf(s - mx) : 0.f;
    sc[t] = p;
    float su = p;
#pragma unroll
    for (int off = 16; off; off >>= 1) su += __shfl_xor_sync(0xffffffffu, su, off);
    __syncthreads();   // everyone done reading red[0]; sc written
    if ((t & 31) == 0) red[t >> 5] = su;
    __syncthreads();
    if (t < 32) {
        float s2 = (t < 8) ? red[t] : 0.f;
#pragma unroll
        for (int off = 4; off; off >>= 1) s2 += __shfl_xor_sync(0xffffffffu, s2, off);
        if (t == 0) red[0] = s2;
    }
    __syncthreads();
    const float inv = 1.f / red[0];

    // P @ V : thread t -> (dim d = t&63, partial part = t>>6)
    const int d = t & 63;
    const int part = t >> 6;
    float a = 0.f;
    const float* vb = v + (size_t)h * HDIM + d;
    for (int j = part; j < cnt; j += 4)
        a = fmaf(sc[j], vb[(size_t)(j0 + j) * DMODEL], a);
    osum[part][d] = a;
    __syncthreads();
    if (part == 0) {
        float r = (osum[0][d] + osum[1][d] + osum[2][d] + osum[3][d]) * inv;
        if (!isfinite(r)) r = 0.f;
        o[(size_t)i * DMODEL + h * HDIM + d] = r;
    }
}

// ---------------- SwiGLU elementwise: z1 = silu(z1) * z3 ----------------
__global__ void swiglu_kernel(float* __restrict__ z1, const float* __restrict__ z3, int n) {
    int idx = blockIdx.x * blockDim.x + threadIdx.x;
    if (idx < n) {
        float a = z1[idx];
        float b = z3[idx];
        float s = a / (1.f + expf(-a));
        z1[idx] = s * b;
    }
}

// ---------------- SGEMM: C[m,n] = sum_k A[m,k] * B[n,k] + bias[n] ----------------
// MODE 0: store; MODE 1: C += ...; MODE 2: store clipped to [-50, 50]
template <int MODE>
__global__ void __launch_bounds__(256, 2)
sgemm_kernel(const float* __restrict__ A, const float* __restrict__ B,
             const float* __restrict__ bias, float* __restrict__ C,
             int M, int N, int K) {
    constexpr int BM = 128, BN = 128, BK = 8;
    __shared__ float As[BK][BM];
    __shared__ float Bs[BK][BN];
    const int bm = blockIdx.y * BM;
    const int bn = blockIdx.x * BN;
    const int tid = threadIdx.x;
    const int lrow = tid >> 1;          // 0..127
    const int lcol = (tid & 1) * 4;     // 0 or 4
    const int tx = tid & 15;
    const int ty = tid >> 4;
    const int cm = ty * 8;
    const int cn = tx * 8;

    float acc[8][8];
#pragma unroll
    for (int i = 0; i < 8; i++)
#pragma unroll
        for (int j = 0; j < 8; j++) acc[i][j] = 0.f;

    const float* Aptr = A + (size_t)(bm + lrow) * K + lcol;
    const float* Bptr = B + (size_t)(bn + lrow) * K + lcol;
    const bool bvalid = (bn + lrow) < N;   // M always multiple of 128 here

    for (int k0 = 0; k0 < K; k0 += BK) {
        float4 a4 = *(const float4*)(Aptr + k0);
        float4 b4 = make_float4(0.f, 0.f, 0.f, 0.f);
        if (bvalid) b4 = *(const float4*)(Bptr + k0);
        As[lcol + 0][lrow] = a4.x;
        As[lcol + 1][lrow] = a4.y;
        As[lcol + 2][lrow] = a4.z;
        As[lcol + 3][lrow] = a4.w;
        Bs[lcol + 0][lrow] = b4.x;
        Bs[lcol + 1][lrow] = b4.y;
        Bs[lcol + 2][lrow] = b4.z;
        Bs[lcol + 3][lrow] = b4.w;
        __syncthreads();
#pragma unroll
        for (int kk = 0; kk < BK; kk++) {
            float ar[8], br[8];
#pragma unroll
            for (int i = 0; i < 8; i++) ar[i] = As[kk][cm + i];
#pragma unroll
            for (int j = 0; j < 8; j++) br[j] = Bs[kk][cn + j];
#pragma unroll
            for (int i = 0; i < 8; i++)
#pragma unroll
                for (int j = 0; j < 8; j++) acc[i][j] = fmaf(ar[i], br[j], acc[i][j]);
        }
        __syncthreads();
    }

#pragma unroll
    for (int i = 0; i < 8; i++) {
        size_t m = (size_t)(bm + cm + i);
#pragma unroll
        for (int j = 0; j < 8; j++) {
            int n = bn + cn + j;
            if (n < N) {
                float r = acc[i][j] + bias[n];
                if (MODE == 1) r += C[m * (size_t)N + n];
                if (MODE == 2) r = fminf(fmaxf(r, -50.f), 50.f);
                C[m * (size_t)N + n] = r;
            }
        }
    }
}

template <int MODE>
static void launch_gemm(const float* A, const float* B, const float* bias, float* C,
                        int M, int N, int K) {
    dim3 grid((N + 127) / 128, (M + 127) / 128);
    sgemm_kernel<MODE><<<grid, 256>>>(A, B, bias, C, M, N, K);
}

// ---------------- driver ----------------
extern "C" void kernel_launch(void* const* d_in, const int* in_sizes, int n_in,
                              void* d_out, int out_size) {
    const int*   tokens  = (const int*)d_in[0];
    const float* embed_w = (const float*)d_in[1];
    const float* ln1_w   = (const float*)d_in[2];
    const float* ln2_w   = (const float*)d_in[3];
    const float* wq_w    = (const float*)d_in[4];
    const float* wq_b    = (const float*)d_in[5];
    const float* wk_w    = (const float*)d_in[6];
    const float* wk_b    = (const float*)d_in[7];
    const float* wv_w    = (const float*)d_in[8];
    const float* wv_b    = (const float*)d_in[9];
    const float* wo_w    = (const float*)d_in[10];
    const float* wo_b    = (const float*)d_in[11];
    const float* qn_w    = (const float*)d_in[12];
    const float* kn_w    = (const float*)d_in[13];
    const float* w1_w    = (const float*)d_in[14];
    const float* w1_b    = (const float*)d_in[15];
    const float* w2_w    = (const float*)d_in[16];
    const float* w2_b    = (const float*)d_in[17];
    const float* w3_w    = (const float*)d_in[18];
    const float* w3_b    = (const float*)d_in[19];
    const float* lnf_w   = (const float*)d_in[20];
    const float* lm_w    = (const float*)d_in[21];
    const float* lm_b    = (const float*)d_in[22];
    float* out = (float*)d_out;

    float *x, *xn, *q, *k, *v, *attn, *z1, *z3;
    cudaGetSymbolAddress((void**)&x, g_x);
    cudaGetSymbolAddress((void**)&xn, g_xn);
    cudaGetSymbolAddress((void**)&q, g_q);
    cudaGetSymbolAddress((void**)&k, g_k);
    cudaGetSymbolAddress((void**)&v, g_v);
    cudaGetSymbolAddress((void**)&attn, g_attn);
    cudaGetSymbolAddress((void**)&z1, g_z1);
    cudaGetSymbolAddress((void**)&z3, g_z3);

    embed_kernel<<<LSEQ, 256>>>(tokens, embed_w, x);

    for (int l = 0; l < NLYR; l++) {
        const size_t dd = (size_t)l * DMODEL * DMODEL;
        rmsnorm_kernel<<<LSEQ, 256>>>(x, ln1_w + (size_t)l * DMODEL, xn);
        launch_gemm<0>(xn, wq_w + dd, wq_b + (size_t)l * DMODEL, q, LSEQ, DMODEL, DMODEL);
        launch_gemm<0>(xn, wk_w + dd, wk_b + (size_t)l * DMODEL, k, LSEQ, DMODEL, DMODEL);
        launch_gemm<0>(xn, wv_w + dd, wv_b + (size_t)l * DMODEL, v, LSEQ, DMODEL, DMODEL);
        rmsnorm_head_kernel<<<(LSEQ * NHEAD) / 8, 256>>>(q, qn_w + (size_t)l * HDIM);
        rmsnorm_head_kernel<<<(LSEQ * NHEAD) / 8, 256>>>(k, kn_w + (size_t)l * HDIM);
        attn_kernel<<<dim3(LSEQ, NHEAD), 256>>>(q, k, v, attn);
        launch_gemm<1>(attn, wo_w + dd, wo_b + (size_t)l * DMODEL, x, LSEQ, DMODEL, DMODEL);

        rmsnorm_kernel<<<LSEQ, 256>>>(x, ln2_w + (size_t)l * DMODEL, xn);
        launch_gemm<0>(xn, w1_w + (size_t)l * IDIM * DMODEL, w1_b + (size_t)l * IDIM, z1,
                       LSEQ, IDIM, DMODEL);
        launch_gemm<0>(xn, w3_w + (size_t)l * IDIM * DMODEL, w3_b + (size_t)l * IDIM, z3,
                       LSEQ, IDIM, DMODEL);
        swiglu_kernel<<<(LSEQ * IDIM + 255) / 256, 256>>>(z1, z3, LSEQ * IDIM);
        launch_gemm<1>(z1, w2_w + (size_t)l * DMODEL * IDIM, w2_b + (size_t)l * DMODEL, x,
                       LSEQ, DMODEL, IDIM);
    }

    rmsnorm_kernel<<<LSEQ, 256>>>(x, lnf_w, xn);
    launch_gemm<2>(xn, lm_w, lm_b, out, LSEQ, VDIM, DMODEL);
}

// round 2
// speedup vs baseline: 3.7653x; 3.7653x over previous
#include <cuda_runtime.h>
#include <math.h>

// ---------------- problem constants ----------------
#define LSEQ 2048
#define DMODEL 1024
#define NHEAD 16
#define HDIM 64
#define NLYR 4
#define WIN 256
#define IDIM 3280
#define VDIM 32000
#define EPSV 1e-5f

// ---------------- scratch ----------------
__device__ float g_x[LSEQ * DMODEL];
__device__ float g_xn[LSEQ * DMODEL];
__device__ float g_q[LSEQ * DMODEL];
__device__ float g_k[LSEQ * DMODEL];
__device__ float g_v[LSEQ * DMODEL];
__device__ float g_attn[LSEQ * DMODEL];
__device__ float g_z1[LSEQ * IDIM];
__device__ float g_z3[LSEQ * IDIM];

// ---------------- embedding gather ----------------
__global__ void embed_kernel(const int* __restrict__ tokens,
                             const float* __restrict__ ew,
                             float* __restrict__ x) {
    int i = blockIdx.x;
    int tok = tokens[i];
    const float4* src = (const float4*)(ew + (size_t)tok * DMODEL);
    float4* dst = (float4*)(x + (size_t)i * DMODEL);
    dst[threadIdx.x] = src[threadIdx.x];
}

// ---------------- row RMSNorm (D=1024) ----------------
__global__ void rmsnorm_kernel(const float* __restrict__ x,
                               const float* __restrict__ w,
                               float* __restrict__ y) {
    const int row = blockIdx.x;
    const int t = threadIdx.x;
    const float* xr = x + (size_t)row * DMODEL;
    float v[4];
    float ss = 0.f;
#pragma unroll
    for (int j = 0; j < 4; j++) {
        float a = xr[t + j * 256];
        a = fminf(fmaxf(a, -10000.f), 10000.f);
        v[j] = a;
        ss = fmaf(a, a, ss);
    }
#pragma unroll
    for (int off = 16; off; off >>= 1) ss += __shfl_xor_sync(0xffffffffu, ss, off);
    __shared__ float red[8];
    if ((t & 31) == 0) red[t >> 5] = ss;
    __syncthreads();
    if (t < 32) {
        float s2 = (t < 8) ? red[t] : 0.f;
#pragma unroll
        for (int off = 4; off; off >>= 1) s2 += __shfl_xor_sync(0xffffffffu, s2, off);
        if (t == 0) red[0] = s2;
    }
    __syncthreads();
    float mean = red[0] * (1.f / DMODEL);
    float inv = 1.f / sqrtf(fmaxf(mean, EPSV) + EPSV);
#pragma unroll
    for (int j = 0; j < 4; j++) {
        int c = t + j * 256;
        float r = v[j] * inv * w[c];
        if (!isfinite(r)) r = 0.f;
        y[(size_t)row * DMODEL + c] = r;
    }
}

// ---------------- per-head RMSNorm (64 dims), in place ----------------
__global__ void rmsnorm_head_kernel(float* __restrict__ q, const float* __restrict__ w) {
    int r = blockIdx.x * (blockDim.x >> 5) + (threadIdx.x >> 5);
    int lane = threadIdx.x & 31;
    float* p = q + (size_t)r * HDIM;
    float a0 = p[lane], a1 = p[lane + 32];
    a0 = fminf(fmaxf(a0, -10000.f), 10000.f);
    a1 = fminf(fmaxf(a1, -10000.f), 10000.f);
    float ss = a0 * a0 + a1 * a1;
#pragma unroll
    for (int off = 16; off; off >>= 1) ss += __shfl_xor_sync(0xffffffffu, ss, off);
    float mean = ss * (1.f / HDIM);
    float inv = 1.f / sqrtf(fmaxf(mean, EPSV) + EPSV);
    float r0 = a0 * inv * w[lane];
    float r1 = a1 * inv * w[lane + 32];
    if (!isfinite(r0)) r0 = 0.f;
    if (!isfinite(r1)) r1 = 0.f;
    p[lane] = r0;
    p[lane + 32] = r1;
}

// ---------------- flash-style sliding-window attention ----------------
// block = (head, 32-query tile); 256 threads: thread = (row r=tid>>3, group g=tid&7)
#define QT 32
__global__ void __launch_bounds__(256)
attn2_kernel(const float* __restrict__ q, const float* __restrict__ k,
             const float* __restrict__ v, float* __restrict__ o) {
    const int h = blockIdx.y;
    const int qt = blockIdx.x * QT;
    const int tid = threadIdx.x;
    const int r = tid >> 3;
    const int g = tid & 7;
    const int i = qt + r;

    __shared__ float Qs[QT][65];
    __shared__ float Kt[64][36];   // transposed: [d][j]
    __shared__ float Vs[QT][68];
    __shared__ float Ps[QT][33];

    {
        const float* qp = q + (size_t)i * DMODEL + h * HDIM + g * 8;
#pragma unroll
        for (int t2 = 0; t2 < 8; t2++) Qs[r][g * 8 + t2] = qp[t2];
    }

    float m = -INFINITY, lsum = 0.f;
    float acc[8];
#pragma unroll
    for (int d = 0; d < 8; d++) acc[d] = 0.f;

    int cs = max(0, qt - (WIN - 1)) & ~31;
    for (int jc = cs; jc <= qt + QT - 1; jc += 32) {
        __syncthreads();
        // stage K (transposed) and V chunk
        {
            const int row = tid >> 3;
            const int c0 = (tid & 7) * 8;
            const float* kp = k + (size_t)(jc + row) * DMODEL + h * HDIM + c0;
            const float* vp = v + (size_t)(jc + row) * DMODEL + h * HDIM + c0;
            float4 k0 = *(const float4*)kp;
            float4 k1 = *(const float4*)(kp + 4);
            Kt[c0 + 0][row] = k0.x; Kt[c0 + 1][row] = k0.y;
            Kt[c0 + 2][row] = k0.z; Kt[c0 + 3][row] = k0.w;
            Kt[c0 + 4][row] = k1.x; Kt[c0 + 5][row] = k1.y;
            Kt[c0 + 6][row] = k1.z; Kt[c0 + 7][row] = k1.w;
            *(float4*)&Vs[row][c0] = *(const float4*)vp;
            *(float4*)&Vs[row][c0 + 4] = *(const float4*)(vp + 4);
        }
        __syncthreads();

        // scores for 4 keys j = jc + g*4 + {0..3}
        float s0 = 0.f, s1 = 0.f, s2 = 0.f, s3 = 0.f;
#pragma unroll
        for (int d = 0; d < 64; d++) {
            float4 kd = *(const float4*)&Kt[d][g * 4];
            float qd = Qs[r][d];
            s0 = fmaf(qd, kd.x, s0);
            s1 = fmaf(qd, kd.y, s1);
            s2 = fmaf(qd, kd.z, s2);
            s3 = fmaf(qd, kd.w, s3);
        }
        const int jb = jc + g * 4;
        s0 = ((jb + 0) <= i && (i - (jb + 0)) < WIN) ? s0 * 0.125f : -INFINITY;
        s1 = ((jb + 1) <= i && (i - (jb + 1)) < WIN) ? s1 * 0.125f : -INFINITY;
        s2 = ((jb + 2) <= i && (i - (jb + 2)) < WIN) ? s2 * 0.125f : -INFINITY;
        s3 = ((jb + 3) <= i && (i - (jb + 3)) < WIN) ? s3 * 0.125f : -INFINITY;

        float mc = fmaxf(fmaxf(s0, s1), fmaxf(s2, s3));
        mc = fmaxf(mc, __shfl_xor_sync(0xffffffffu, mc, 1));
        mc = fmaxf(mc, __shfl_xor_sync(0xffffffffu, mc, 2));
        mc = fmaxf(mc, __shfl_xor_sync(0xffffffffu, mc, 4));
        float mnew = fmaxf(m, mc);

        float alpha = 1.f;
        float p0 = 0.f, p1 = 0.f, p2 = 0.f, p3 = 0.f;
        if (mnew != -INFINITY) {
            alpha = (m == -INFINITY) ? 0.f : expf(m - mnew);
            p0 = expf(s0 - mnew);
            p1 = expf(s1 - mnew);
            p2 = expf(s2 - mnew);
            p3 = expf(s3 - mnew);
            m = mnew;
        }
        Ps[r][g * 4 + 0] = p0;
        Ps[r][g * 4 + 1] = p1;
        Ps[r][g * 4 + 2] = p2;
        Ps[r][g * 4 + 3] = p3;
        lsum = lsum * alpha + (p0 + p1 + p2 + p3);
        __syncwarp();

#pragma unroll
        for (int d = 0; d < 8; d++) acc[d] *= alpha;
#pragma unroll 4
        for (int j = 0; j < 32; j++) {
            float p = Ps[r][j];
            float4 v0 = *(const float4*)&Vs[j][g * 8];
            float4 v1 = *(const float4*)&Vs[j][g * 8 + 4];
            acc[0] = fmaf(p, v0.x, acc[0]);
            acc[1] = fmaf(p, v0.y, acc[1]);
            acc[2] = fmaf(p, v0.z, acc[2]);
            acc[3] = fmaf(p, v0.w, acc[3]);
            acc[4] = fmaf(p, v1.x, acc[4]);
            acc[5] = fmaf(p, v1.y, acc[5]);
            acc[6] = fmaf(p, v1.z, acc[6]);
            acc[7] = fmaf(p, v1.w, acc[7]);
        }
    }

    float lt = lsum;
    lt += __shfl_xor_sync(0xffffffffu, lt, 1);
    lt += __shfl_xor_sync(0xffffffffu, lt, 2);
    lt += __shfl_xor_sync(0xffffffffu, lt, 4);
    float invl = 1.f / lt;
    float* op = o + (size_t)i * DMODEL + h * HDIM + g * 8;
#pragma unroll
    for (int d = 0; d < 8; d++) {
        float rv = acc[d] * invl;
        if (!isfinite(rv)) rv = 0.f;
        op[d] = rv;
    }
}

// ---------------- SwiGLU elementwise ----------------
__global__ void swiglu_kernel(float* __restrict__ z1, const float* __restrict__ z3, int n) {
    int idx = blockIdx.x * blockDim.x + threadIdx.x;
    if (idx < n) {
        float a = z1[idx];
        float b = z3[idx];
        float s = a / (1.f + expf(-a));
        z1[idx] = s * b;
    }
}

// ---------------- tf32 tensor-core GEMM ----------------
// C[m,n] = sum_k A[m,k]*B[n,k] + bias[n]; MODE 0: store, 1: C+=, 2: clip±50
__device__ __forceinline__ float to_tf32(float x) {
    unsigned r;
    asm("cvt.rna.tf32.f32 %0, %1;" : "=r"(r) : "f"(x));
    return __uint_as_float(r);
}

__device__ __forceinline__ void mma_tf32(float* c, const unsigned* a, const unsigned* b) {
    asm volatile(
        "mma.sync.aligned.m16n8k8.row.col.f32.tf32.tf32.f32 "
        "{%0,%1,%2,%3}, {%4,%5,%6,%7}, {%8,%9}, {%0,%1,%2,%3};\n"
        : "+f"(c[0]), "+f"(c[1]), "+f"(c[2]), "+f"(c[3])
        : "r"(a[0]), "r"(a[1]), "r"(a[2]), "r"(a[3]), "r"(b[0]), "r"(b[1]));
}

template <int MODE>
__global__ void __launch_bounds__(256, 2)
tgemm_kernel(const float* __restrict__ A,
             const float* __restrict__ B0, const float* __restrict__ B1,
             const float* __restrict__ B2,
             const float* __restrict__ g0, const float* __restrict__ g1,
             const float* __restrict__ g2,
             float* __restrict__ C0, float* __restrict__ C1, float* __restrict__ C2,
             int M, int N, int K) {
    const float* Bw   = (blockIdx.z == 0) ? B0 : (blockIdx.z == 1 ? B1 : B2);
    const float* bias = (blockIdx.z == 0) ? g0 : (blockIdx.z == 1 ? g1 : g2);
    float*       C    = (blockIdx.z == 0) ? C0 : (blockIdx.z == 1 ? C1 : C2);

    __shared__ float As[2][128][20];
    __shared__ float Bs[2][128][20];

    const int tid = threadIdx.x;
    const int bm = blockIdx.y * 128, bn = blockIdx.x * 128;
    const int warp = tid >> 5, lane = tid & 31;
    const int wm = (warp & 1) * 64, wn = (warp >> 1) * 32;
    const int gid = lane >> 2, tg = lane & 3;

    const int lr = tid >> 1;
    const int lc = (tid & 1) * 8;
    const float* Ag = A + (size_t)(bm + lr) * K + lc;
    const float* Bg = Bw + (size_t)(bn + lr) * K + lc;
    const bool bva = (bn + lr) < N;

    float4 ra0 = *(const float4*)Ag;
    float4 ra1 = *(const float4*)(Ag + 4);
    float4 rb0 = make_float4(0.f, 0.f, 0.f, 0.f);
    float4 rb1 = make_float4(0.f, 0.f, 0.f, 0.f);
    if (bva) {
        rb0 = *(const float4*)Bg;
        rb1 = *(const float4*)(Bg + 4);
    }

    float acc[4][4][4];
#pragma unroll
    for (int a = 0; a < 4; a++)
#pragma unroll
        for (int b = 0; b < 4; b++)
#pragma unroll
            for (int c = 0; c < 4; c++) acc[a][b][c] = 0.f;

    int buf = 0;
    for (int k0 = 0; k0 < K; k0 += 16) {
        As[buf][lr][lc + 0] = to_tf32(ra0.x);
        As[buf][lr][lc + 1] = to_tf32(ra0.y);
        As[buf][lr][lc + 2] = to_tf32(ra0.z);
        As[buf][lr][lc + 3] = to_tf32(ra0.w);
        As[buf][lr][lc + 4] = to_tf32(ra1.x);
        As[buf][lr][lc + 5] = to_tf32(ra1.y);
        As[buf][lr][lc + 6] = to_tf32(ra1.z);
        As[buf][lr][lc + 7] = to_tf32(ra1.w);
        Bs[buf][lr][lc + 0] = to_tf32(rb0.x);
        Bs[buf][lr][lc + 1] = to_tf32(rb0.y);
        Bs[buf][lr][lc + 2] = to_tf32(rb0.z);
        Bs[buf][lr][lc + 3] = to_tf32(rb0.w);
        Bs[buf][lr][lc + 4] = to_tf32(rb1.x);
        Bs[buf][lr][lc + 5] = to_tf32(rb1.y);
        Bs[buf][lr][lc + 6] = to_tf32(rb1.z);
        Bs[buf][lr][lc + 7] = to_tf32(rb1.w);

        if (k0 + 16 < K) {
            ra0 = *(const float4*)(Ag + k0 + 16);
            ra1 = *(const float4*)(Ag + k0 + 20);
            if (bva) {
                rb0 = *(const float4*)(Bg + k0 + 16);
                rb1 = *(const float4*)(Bg + k0 + 20);
            }
        }
        __syncthreads();

#pragma unroll
        for (int ks = 0; ks < 2; ks++) {
            const int kk = ks * 8;
            unsigned af[4][4], bf[4][2];
#pragma unroll
            for (int mi = 0; mi < 4; mi++) {
                const float* p = &As[buf][wm + mi * 16 + gid][kk + tg];
                af[mi][0] = __float_as_uint(p[0]);
                af[mi][1] = __float_as_uint(p[8 * 20]);
                af[mi][2] = __float_as_uint(p[4]);
                af[mi][3] = __float_as_uint(p[8 * 20 + 4]);
            }
#pragma unroll
            for (int ni = 0; ni < 4; ni++) {
                const float* p = &Bs[buf][wn + ni * 8 + gid][kk + tg];
                bf[ni][0] = __float_as_uint(p[0]);
                bf[ni][1] = __float_as_uint(p[4]);
            }
#pragma unroll
            for (int mi = 0; mi < 4; mi++)
#pragma unroll
                for (int ni = 0; ni < 4; ni++)
                    mma_tf32(acc[mi][ni], af[mi], bf[ni]);
        }
        buf ^= 1;
    }

    // epilogue
#pragma unroll
    for (int mi = 0; mi < 4; mi++) {
        const int r0 = bm + wm + mi * 16 + gid;
#pragma unroll
        for (int ni = 0; ni < 4; ni++) {
            const int c0 = bn + wn + ni * 8 + tg * 2;
            if (c0 < N) {
                const float b0v = bias[c0];
                const float b1v = bias[c0 + 1];
                float* p0 = C + (size_t)r0 * N + c0;
                float* p1 = C + (size_t)(r0 + 8) * N + c0;
                float v00 = acc[mi][ni][0] + b0v;
                float v01 = acc[mi][ni][1] + b1v;
                float v10 = acc[mi][ni][2] + b0v;
                float v11 = acc[mi][ni][3] + b1v;
                if (MODE == 1) {
                    v00 += p0[0]; v01 += p0[1];
                    v10 += p1[0]; v11 += p1[1];
                }
                if (MODE == 2) {
                    v00 = fminf(fmaxf(v00, -50.f), 50.f);
                    v01 = fminf(fmaxf(v01, -50.f), 50.f);
                    v10 = fminf(fmaxf(v10, -50.f), 50.f);
                    v11 = fminf(fmaxf(v11, -50.f), 50.f);
                }
                p0[0] = v00; p0[1] = v01;
                p1[0] = v10; p1[1] = v11;
            }
        }
    }
}

// ---------------- driver ----------------
extern "C" void kernel_launch(void* const* d_in, const int* in_sizes, int n_in,
                              void* d_out, int out_size) {
    const int*   tokens  = (const int*)d_in[0];
    const float* embed_w = (const float*)d_in[1];
    const float* ln1_w   = (const float*)d_in[2];
    const float* ln2_w   = (const float*)d_in[3];
    const float* wq_w    = (const float*)d_in[4];
    const float* wq_b    = (const float*)d_in[5];
    const float* wk_w    = (const float*)d_in[6];
    const float* wk_b    = (const float*)d_in[7];
    const float* wv_w    = (const float*)d_in[8];
    const float* wv_b    = (const float*)d_in[9];
    const float* wo_w    = (const float*)d_in[10];
    const float* wo_b    = (const float*)d_in[11];
    const float* qn_w    = (const float*)d_in[12];
    const float* kn_w    = (const float*)d_in[13];
    const float* w1_w    = (const float*)d_in[14];
    const float* w1_b    = (const float*)d_in[15];
    const float* w2_w    = (const float*)d_in[16];
    const float* w2_b    = (const float*)d_in[17];
    const float* w3_w    = (const float*)d_in[18];
    const float* w3_b    = (const float*)d_in[19];
    const float* lnf_w   = (const float*)d_in[20];
    const float* lm_w    = (const float*)d_in[21];
    const float* lm_b    = (const float*)d_in[22];
    float* out = (float*)d_out;

    float *x, *xn, *q, *k, *v, *attn, *z1, *z3;
    cudaGetSymbolAddress((void**)&x, g_x);
    cudaGetSymbolAddress((void**)&xn, g_xn);
    cudaGetSymbolAddress((void**)&q, g_q);
    cudaGetSymbolAddress((void**)&k, g_k);
    cudaGetSymbolAddress((void**)&v, g_v);
    cudaGetSymbolAddress((void**)&attn, g_attn);
    cudaGetSymbolAddress((void**)&z1, g_z1);
    cudaGetSymbolAddress((void**)&z3, g_z3);

    embed_kernel<<<LSEQ, 256>>>(tokens, embed_w, x);

    for (int l = 0; l < NLYR; l++) {
        const size_t dd = (size_t)l * DMODEL * DMODEL;
        const size_t db = (size_t)l * DMODEL;

        rmsnorm_kernel<<<LSEQ, 256>>>(x, ln1_w + db, xn);
        // fused QKV (grid.z = 3)
        tgemm_kernel<0><<<dim3(DMODEL / 128, LSEQ / 128, 3), 256>>>(
            xn, wq_w + dd, wk_w + dd, wv_w + dd,
            wq_b + db, wk_b + db, wv_b + db,
            q, k, v, LSEQ, DMODEL, DMODEL);
        rmsnorm_head_kernel<<<(LSEQ * NHEAD) / 8, 256>>>(q, qn_w + (size_t)l * HDIM);
        rmsnorm_head_kernel<<<(LSEQ * NHEAD) / 8, 256>>>(k, kn_w + (size_t)l * HDIM);
        attn2_kernel<<<dim3(LSEQ / QT, NHEAD), 256>>>(q, k, v, attn);
        tgemm_kernel<1><<<dim3(DMODEL / 128, LSEQ / 128, 1), 256>>>(
            attn, wo_w + dd, wo_w + dd, wo_w + dd,
            wo_b + db, wo_b + db, wo_b + db,
            x, x, x, LSEQ, DMODEL, DMODEL);

        rmsnorm_kernel<<<LSEQ, 256>>>(x, ln2_w + db, xn);
        // fused w1/w3 (grid.z = 2)
        tgemm_kernel<0><<<dim3((IDIM + 127) / 128, LSEQ / 128, 2), 256>>>(
            xn, w1_w + (size_t)l * IDIM * DMODEL, w3_w + (size_t)l * IDIM * DMODEL,
            w3_w + (size_t)l * IDIM * DMODEL,
            w1_b + (size_t)l * IDIM, w3_b + (size_t)l * IDIM, w3_b + (size_t)l * IDIM,
            z1, z3, z3, LSEQ, IDIM, DMODEL);
        swiglu_kernel<<<(LSEQ * IDIM + 255) / 256, 256>>>(z1, z3, LSEQ * IDIM);
        tgemm_kernel<1><<<dim3(DMODEL / 128, LSEQ / 128, 1), 256>>>(
            z1, w2_w + (size_t)l * DMODEL * IDIM, w2_w + (size_t)l * DMODEL * IDIM,
            w2_w + (size_t)l * DMODEL * IDIM,
            w2_b + db, w2_b + db, w2_b + db,
            x, x, x, LSEQ, DMODEL, IDIM);
    }

    rmsnorm_kernel<<<LSEQ, 256>>>(x, lnf_w, xn);
    tgemm_kernel<2><<<dim3(VDIM / 128, LSEQ / 128, 1), 256>>>(
        xn, lm_w, lm_w, lm_w, lm_b, lm_b, lm_b,
        out, out, out, LSEQ, VDIM, DMODEL);
}